// round 3
// baseline (speedup 1.0000x reference)
#include <cuda_runtime.h>
#include <math.h>

#define N_ROWS  8192
#define N_PROP  2000
#define THREADS 256

// d_in[0]=rois (N,4), d_in[1]=rpn_rois (N,NP,5), d_in[2]=scores (N,NP,2)
// d_out = [sel_rpn_rois (N,4) | sel_scores (N,1)]

struct RefStats { float x, y, s, inv_s, r_max, piw, wsq; };

__device__ __forceinline__ float rcp_approx(float a) {
    float r; asm("rcp.approx.ftz.f32 %0, %1;" : "=f"(r) : "f"(a)); return r;
}
__device__ __forceinline__ float ex2_approx(float a) {
    float r; asm("ex2.approx.ftz.f32 %0, %1;" : "=f"(r) : "f"(a)); return r;
}

// exp(y) for y <= 0, ~2ulp: range-reduce to ex2.approx on [-0.5, 0.5]
__device__ __forceinline__ float fast_exp_neg(float y) {
    float z  = fmaxf(y * 1.4426950408889634f, -127.0f);
    float fn = rintf(z);
    float m  = ex2_approx(z - fn);
    float sc = __int_as_float(((int)fn + 127) << 23);  // 2^n, n in [-127, 0]
    return m * sc;
}

// cos(t/2) on t in [0, pi] via Taylor (7 coeffs, err < 1e-8); hanning = P^2
__device__ __forceinline__ float hann_from_t(float t) {
    float th = t * 0.5f;
    float u  = th * th;
    float P = 2.0876757e-9f;
    P = fmaf(P, u, -1.1470746e-11f * 0.0f - 2.7557319e-7f); // c5
    P = fmaf(P, u,  2.4801587e-5f);
    P = fmaf(P, u, -1.3888889e-3f);
    P = fmaf(P, u,  4.1666667e-2f);
    P = fmaf(P, u, -0.5f);
    P = fmaf(P, u,  1.0f);
    return P * P;
}

__device__ __forceinline__ float prop_score(const RefStats& R,
                                            float a0, float a1, float a2, float a3,
                                            float sc)
{
    const float x_ = (a0 + a2) * 0.5f;
    const float y_ = (a1 + a3) * 0.5f;
    const float w_ = fabsf(a0 - a2) + 1e-4f;
    const float h_ = fabsf(a1 - a3) + 1e-4f;
    const float p_ = (w_ + h_) * 0.5f;
    const float q  = (w_ + p_) * (h_ + p_);
    const float s_ = q * rsqrtf(q);                 // sqrt approx (~1.5e-7)

    const float smax = fmaxf(R.s * rcp_approx(s_), s_ * R.inv_s);
    const float pen  = fast_exp_neg(fmaf(smax * R.r_max, -0.055f, 0.055f));

    const float dx  = R.x - x_;
    const float dy  = R.y - y_;
    const float d2  = fmaf(dx, dx, dy * dy);
    const float d2g = fmaxf(d2, 1e-36f);
    const float dist = d2g * rsqrtf(d2g);
    const float t   = fminf(dist * R.piw, 3.2f);    // clamp: discarded lanes stay finite
    float han = hann_from_t(t);
    han = (d2 > R.wsq) ? 0.0f : han;

    return fmaf(sc, pen, 0.42f * han);
}

__global__ __launch_bounds__(THREADS)
void trnms_kernel(const float* __restrict__ rois,
                  const float* __restrict__ rpn,
                  const float* __restrict__ scores,
                  float* __restrict__ out)
{
    const int row = blockIdx.x;
    const int tid = threadIdx.x;

    RefStats R;
    {
        const float4 rr = *reinterpret_cast<const float4*>(rois + (size_t)row * 4);
        R.x = (rr.x + rr.z) * 0.5f;
        R.y = (rr.y + rr.w) * 0.5f;
        const float w = fabsf(rr.x - rr.z) + 1e-4f;
        const float h = fabsf(rr.y - rr.w) + 1e-4f;
        const float p = (w + h) * 0.5f;
        R.s = sqrtf((w + p) * (h + p));             // row constants: precise
        R.inv_s = __fdiv_rn(1.0f, R.s);
        const float ratio = __fdiv_rn(w, h);
        R.r_max = fmaxf(ratio, __fdiv_rn(1.0f, ratio));
        const float window = R.s * 2.0f;
        R.piw = __fdiv_rn(3.14159274101257324219f, window);
        R.wsq = window * window;
    }

    const float* rbase = rpn    + (long long)row * (N_PROP * 5);
    const float* sbase = scores + (long long)row * (N_PROP * 2);

    float best = -INFINITY;
    int   bidx = 0x7fffffff;

    #pragma unroll 2
    for (int j = tid; j < N_PROP; j += THREADS) {
        const float* q = rbase + j * 5;
        const float a0 = __ldg(q + 1);
        const float a1 = __ldg(q + 2);
        const float a2 = __ldg(q + 3);
        const float a3 = __ldg(q + 4);
        const float sc = __ldg(sbase + j * 2 + 1);

        const float pw = prop_score(R, a0, a1, a2, a3, sc);
        if (pw > best) { best = pw; bidx = j; }      // strict > : first index wins
    }

    // ---- block argmax reduction, first-index wins on ties ----
    const int lane = tid & 31;
    const int wid  = tid >> 5;

    #pragma unroll
    for (int off = 16; off > 0; off >>= 1) {
        const float ov = __shfl_down_sync(0xffffffffu, best, off);
        const int   oi = __shfl_down_sync(0xffffffffu, bidx, off);
        if (ov > best || (ov == best && oi < bidx)) { best = ov; bidx = oi; }
    }

    __shared__ float sv[THREADS / 32];
    __shared__ int   si[THREADS / 32];
    if (lane == 0) { sv[wid] = best; si[wid] = bidx; }
    __syncthreads();

    if (wid == 0) {
        best = (lane < THREADS / 32) ? sv[lane] : -INFINITY;
        bidx = (lane < THREADS / 32) ? si[lane] : 0x7fffffff;
        #pragma unroll
        for (int off = (THREADS / 32) / 2; off > 0; off >>= 1) {
            const float ov = __shfl_down_sync(0xffffffffu, best, off);
            const int   oi = __shfl_down_sync(0xffffffffu, bidx, off);
            if (ov > best || (ov == best && oi < bidx)) { best = ov; bidx = oi; }
        }
        if (lane == 0) {
            const float* q = rbase + (long long)bidx * 5;
            float* o = out + (size_t)row * 4;
            o[0] = q[1];
            o[1] = q[2];
            o[2] = q[3];
            o[3] = q[4];
            out[(size_t)N_ROWS * 4 + row] = sbase[bidx * 2 + 1];
        }
    }
}

extern "C" void kernel_launch(void* const* d_in, const int* in_sizes, int n_in,
                              void* d_out, int out_size)
{
    const float* rois   = (const float*)d_in[0];
    const float* rpn    = (const float*)d_in[1];
    const float* scores = (const float*)d_in[2];
    float* out = (float*)d_out;

    trnms_kernel<<<N_ROWS, THREADS>>>(rois, rpn, scores, out);
}

// round 4
// speedup vs baseline: 1.1601x; 1.1601x over previous
#include <cuda_runtime.h>
#include <math.h>

#define N_ROWS  8192
#define N_PROP  2000
#define THREADS 256

// d_in[0]=rois (N,4), d_in[1]=rpn_rois (N,NP,5), d_in[2]=scores (N,NP,2)
// d_out = [sel_rpn_rois (N,4) | sel_scores (N,1)]

struct RefStats { float x, y, s, inv_s, r_max, piw, wsq; };

__device__ __forceinline__ float rcp_approx(float a) {
    float r; asm("rcp.approx.ftz.f32 %0, %1;" : "=f"(r) : "f"(a)); return r;
}
__device__ __forceinline__ float ex2_approx(float a) {
    float r; asm("ex2.approx.ftz.f32 %0, %1;" : "=f"(r) : "f"(a)); return r;
}

// exp(y) for y <= 0, ~2ulp: range-reduce to ex2.approx on [-0.5, 0.5]
__device__ __forceinline__ float fast_exp_neg(float y) {
    float z  = fmaxf(y * 1.4426950408889634f, -127.0f);
    float fn = rintf(z);
    float m  = ex2_approx(z - fn);
    float sc = __int_as_float(((int)fn + 127) << 23);
    return m * sc;
}

// hanning(t) = cos^2(t/2), Taylor on t/2 in [0, 1.6], err < 1e-8
__device__ __forceinline__ float hann_from_t(float t) {
    float th = t * 0.5f;
    float u  = th * th;
    float P = 2.0876757e-9f;
    P = fmaf(P, u, -2.7557319e-7f);
    P = fmaf(P, u,  2.4801587e-5f);
    P = fmaf(P, u, -1.3888889e-3f);
    P = fmaf(P, u,  4.1666667e-2f);
    P = fmaf(P, u, -0.5f);
    P = fmaf(P, u,  1.0f);
    return P * P;
}

__device__ __forceinline__ float prop_score(const RefStats& R,
                                            float a0, float a1, float a2, float a3,
                                            float sc)
{
    const float x_ = (a0 + a2) * 0.5f;
    const float y_ = (a1 + a3) * 0.5f;
    const float w_ = fabsf(a0 - a2) + 1e-4f;
    const float h_ = fabsf(a1 - a3) + 1e-4f;
    const float p_ = (w_ + h_) * 0.5f;
    const float q  = (w_ + p_) * (h_ + p_);
    const float s_ = q * rsqrtf(q);

    const float smax = fmaxf(R.s * rcp_approx(s_), s_ * R.inv_s);
    const float pen  = fast_exp_neg(fmaf(smax * R.r_max, -0.055f, 0.055f));

    const float dx  = R.x - x_;
    const float dy  = R.y - y_;
    const float d2  = fmaf(dx, dx, dy * dy);
    const float d2g = fmaxf(d2, 1e-36f);
    const float dist = d2g * rsqrtf(d2g);
    const float t   = fminf(dist * R.piw, 3.2f);
    float han = hann_from_t(t);
    han = (d2 > R.wsq) ? 0.0f : han;

    return fmaf(sc, pen, 0.42f * han);
}

__global__ __launch_bounds__(THREADS)
void trnms_kernel(const float* __restrict__ rois,
                  const float* __restrict__ rpn,
                  const float* __restrict__ scores,
                  float* __restrict__ out)
{
    const int row = blockIdx.x;
    const int tid = threadIdx.x;

    RefStats R;
    {
        const float4 rr = *reinterpret_cast<const float4*>(rois + (size_t)row * 4);
        R.x = (rr.x + rr.z) * 0.5f;
        R.y = (rr.y + rr.w) * 0.5f;
        const float w = fabsf(rr.x - rr.z) + 1e-4f;
        const float h = fabsf(rr.y - rr.w) + 1e-4f;
        const float p = (w + h) * 0.5f;
        R.s = sqrtf((w + p) * (h + p));
        R.inv_s = __fdiv_rn(1.0f, R.s);
        const float ratio = __fdiv_rn(w, h);
        R.r_max = fmaxf(ratio, __fdiv_rn(1.0f, ratio));
        const float window = R.s * 2.0f;
        R.piw = __fdiv_rn(3.14159274101257324219f, window);
        R.wsq = window * window;
    }

    const float* rbase = rpn    + (long long)row * (N_PROP * 5);
    const float* sbase = scores + (long long)row * (N_PROP * 2);

    float best = -INFINITY;
    int   bidx = 0x7fffffff;

    // ---- software-pipelined loop: prefetch next iteration before computing ----
    int j = tid;                     // tid < 256 < N_PROP, first load always valid
    float c0 = __ldg(rbase + j * 5 + 1);
    float c1 = __ldg(rbase + j * 5 + 2);
    float c2 = __ldg(rbase + j * 5 + 3);
    float c3 = __ldg(rbase + j * 5 + 4);
    float cs = __ldg(sbase + j * 2 + 1);

    while (j < N_PROP) {
        const int jn = j + THREADS;
        float n0 = 0.f, n1 = 0.f, n2 = 0.f, n3 = 0.f, ns = 0.f;
        if (jn < N_PROP) {           // predicated prefetch, issued before the math chain
            n0 = __ldg(rbase + jn * 5 + 1);
            n1 = __ldg(rbase + jn * 5 + 2);
            n2 = __ldg(rbase + jn * 5 + 3);
            n3 = __ldg(rbase + jn * 5 + 4);
            ns = __ldg(sbase + jn * 2 + 1);
        }

        const float pw = prop_score(R, c0, c1, c2, c3, cs);
        if (pw > best) { best = pw; bidx = j; }     // strict > : first index wins

        c0 = n0; c1 = n1; c2 = n2; c3 = n3; cs = ns;
        j = jn;
    }

    // ---- block argmax reduction, first-index wins on ties ----
    const int lane = tid & 31;
    const int wid  = tid >> 5;

    #pragma unroll
    for (int off = 16; off > 0; off >>= 1) {
        const float ov = __shfl_down_sync(0xffffffffu, best, off);
        const int   oi = __shfl_down_sync(0xffffffffu, bidx, off);
        if (ov > best || (ov == best && oi < bidx)) { best = ov; bidx = oi; }
    }

    __shared__ float sv[THREADS / 32];
    __shared__ int   si[THREADS / 32];
    if (lane == 0) { sv[wid] = best; si[wid] = bidx; }
    __syncthreads();

    if (wid == 0) {
        best = (lane < THREADS / 32) ? sv[lane] : -INFINITY;
        bidx = (lane < THREADS / 32) ? si[lane] : 0x7fffffff;
        #pragma unroll
        for (int off = (THREADS / 32) / 2; off > 0; off >>= 1) {
            const float ov = __shfl_down_sync(0xffffffffu, best, off);
            const int   oi = __shfl_down_sync(0xffffffffu, bidx, off);
            if (ov > best || (ov == best && oi < bidx)) { best = ov; bidx = oi; }
        }
        if (lane == 0) {
            const float* q = rbase + (long long)bidx * 5;
            float* o = out + (size_t)row * 4;
            o[0] = q[1];
            o[1] = q[2];
            o[2] = q[3];
            o[3] = q[4];
            out[(size_t)N_ROWS * 4 + row] = sbase[bidx * 2 + 1];
        }
    }
}

extern "C" void kernel_launch(void* const* d_in, const int* in_sizes, int n_in,
                              void* d_out, int out_size)
{
    const float* rois   = (const float*)d_in[0];
    const float* rpn    = (const float*)d_in[1];
    const float* scores = (const float*)d_in[2];
    float* out = (float*)d_out;

    trnms_kernel<<<N_ROWS, THREADS>>>(rois, rpn, scores, out);
}

// round 5
// speedup vs baseline: 1.1834x; 1.0201x over previous
#include <cuda_runtime.h>
#include <math.h>

#define N_ROWS  8192
#define N_PROP  2000
#define THREADS 256

// d_in[0]=rois (N,4), d_in[1]=rpn_rois (N,NP,5), d_in[2]=scores (N,NP,2)
// d_out = [sel_rpn_rois (N,4) | sel_scores (N,1)]

struct RefStats { float x, y, s, inv_s, r_max, piw, wsq; };

__device__ __forceinline__ float rcp_approx(float a) {
    float r; asm("rcp.approx.ftz.f32 %0, %1;" : "=f"(r) : "f"(a)); return r;
}
__device__ __forceinline__ float ex2_approx(float a) {
    float r; asm("ex2.approx.ftz.f32 %0, %1;" : "=f"(r) : "f"(a)); return r;
}

// exp(y) for y <= 0, ~2ulp
__device__ __forceinline__ float fast_exp_neg(float y) {
    float z  = fmaxf(y * 1.4426950408889634f, -127.0f);
    float fn = rintf(z);
    float m  = ex2_approx(z - fn);
    float sc = __int_as_float(((int)fn + 127) << 23);
    return m * sc;
}

// hanning(t) = cos^2(t/2), Taylor on t/2 in [0, 1.6], err < 1e-8
__device__ __forceinline__ float hann_from_t(float t) {
    float th = t * 0.5f;
    float u  = th * th;
    float P = 2.0876757e-9f;
    P = fmaf(P, u, -2.7557319e-7f);
    P = fmaf(P, u,  2.4801587e-5f);
    P = fmaf(P, u, -1.3888889e-3f);
    P = fmaf(P, u,  4.1666667e-2f);
    P = fmaf(P, u, -0.5f);
    P = fmaf(P, u,  1.0f);
    return P * P;
}

__device__ __forceinline__ float prop_score(const RefStats& R,
                                            float a0, float a1, float a2, float a3,
                                            float sc)
{
    const float x_ = (a0 + a2) * 0.5f;
    const float y_ = (a1 + a3) * 0.5f;
    const float w_ = fabsf(a0 - a2) + 1e-4f;
    const float h_ = fabsf(a1 - a3) + 1e-4f;
    const float p_ = (w_ + h_) * 0.5f;
    const float q  = (w_ + p_) * (h_ + p_);
    const float s_ = q * rsqrtf(q);

    const float smax = fmaxf(R.s * rcp_approx(s_), s_ * R.inv_s);
    const float pen  = fast_exp_neg(fmaf(smax * R.r_max, -0.055f, 0.055f));

    const float dx  = R.x - x_;
    const float dy  = R.y - y_;
    const float d2  = fmaf(dx, dx, dy * dy);
    const float d2g = fmaxf(d2, 1e-36f);
    const float dist = d2g * rsqrtf(d2g);
    const float t   = fminf(dist * R.piw, 3.2f);
    float han = hann_from_t(t);
    han = (d2 > R.wsq) ? 0.0f : han;

    return fmaf(sc, pen, 0.42f * han);
}

struct Prop { float a0, a1, a2, a3, sc; };

__device__ __forceinline__ Prop load_prop(const float* __restrict__ rbase,
                                          const float* __restrict__ sbase, int j)
{
    Prop p;
    p.a0 = __ldg(rbase + j * 5 + 1);
    p.a1 = __ldg(rbase + j * 5 + 2);
    p.a2 = __ldg(rbase + j * 5 + 3);
    p.a3 = __ldg(rbase + j * 5 + 4);
    p.sc = __ldg(sbase + j * 2 + 1);
    return p;
}

__global__ __launch_bounds__(THREADS)
void trnms_kernel(const float* __restrict__ rois,
                  const float* __restrict__ rpn,
                  const float* __restrict__ scores,
                  float* __restrict__ out)
{
    const int row = blockIdx.x;
    const int tid = threadIdx.x;

    RefStats R;
    {
        const float4 rr = *reinterpret_cast<const float4*>(rois + (size_t)row * 4);
        R.x = (rr.x + rr.z) * 0.5f;
        R.y = (rr.y + rr.w) * 0.5f;
        const float w = fabsf(rr.x - rr.z) + 1e-4f;
        const float h = fabsf(rr.y - rr.w) + 1e-4f;
        const float p = (w + h) * 0.5f;
        R.s = sqrtf((w + p) * (h + p));
        R.inv_s = __fdiv_rn(1.0f, R.s);
        const float ratio = __fdiv_rn(w, h);
        R.r_max = fmaxf(ratio, __fdiv_rn(1.0f, ratio));
        const float window = R.s * 2.0f;
        R.piw = __fdiv_rn(3.14159274101257324219f, window);
        R.wsq = window * window;
    }

    const float* rbase = rpn    + (long long)row * (N_PROP * 5);
    const float* sbase = scores + (long long)row * (N_PROP * 2);

    float best = -INFINITY;
    int   bidx = 0x7fffffff;

    // ---- 2-wide software pipeline: 10 loads in flight per warp ----
    int j = tid;                                   // tid < 256 < N_PROP
    Prop A = load_prop(rbase, sbase, j);
    Prop B = {0, 0, 0, 0, 0};
    if (j + THREADS < N_PROP) B = load_prop(rbase, sbase, j + THREADS);

    while (j < N_PROP) {
        const int jb = j + THREADS;
        const int jc = j + 2 * THREADS;
        const int jd = j + 3 * THREADS;

        Prop C = {0, 0, 0, 0, 0}, D = {0, 0, 0, 0, 0};
        if (jc < N_PROP) C = load_prop(rbase, sbase, jc);
        if (jd < N_PROP) D = load_prop(rbase, sbase, jd);

        const float pA = prop_score(R, A.a0, A.a1, A.a2, A.a3, A.sc);
        if (pA > best) { best = pA; bidx = j; }             // j < N_PROP by loop guard
        const float pB = prop_score(R, B.a0, B.a1, B.a2, B.a3, B.sc);
        if (jb < N_PROP && pB > best) { best = pB; bidx = jb; }

        A = C; B = D;
        j += 2 * THREADS;
    }

    // ---- block argmax reduction, first-index wins on ties ----
    const int lane = tid & 31;
    const int wid  = tid >> 5;

    #pragma unroll
    for (int off = 16; off > 0; off >>= 1) {
        const float ov = __shfl_down_sync(0xffffffffu, best, off);
        const int   oi = __shfl_down_sync(0xffffffffu, bidx, off);
        if (ov > best || (ov == best && oi < bidx)) { best = ov; bidx = oi; }
    }

    __shared__ float sv[THREADS / 32];
    __shared__ int   si[THREADS / 32];
    if (lane == 0) { sv[wid] = best; si[wid] = bidx; }
    __syncthreads();

    if (wid == 0) {
        best = (lane < THREADS / 32) ? sv[lane] : -INFINITY;
        bidx = (lane < THREADS / 32) ? si[lane] : 0x7fffffff;
        #pragma unroll
        for (int off = (THREADS / 32) / 2; off > 0; off >>= 1) {
            const float ov = __shfl_down_sync(0xffffffffu, best, off);
            const int   oi = __shfl_down_sync(0xffffffffu, bidx, off);
            if (ov > best || (ov == best && oi < bidx)) { best = ov; bidx = oi; }
        }
        if (lane == 0) {
            const float* q = rbase + (long long)bidx * 5;
            float* o = out + (size_t)row * 4;
            o[0] = q[1];
            o[1] = q[2];
            o[2] = q[3];
            o[3] = q[4];
            out[(size_t)N_ROWS * 4 + row] = sbase[bidx * 2 + 1];
        }
    }
}

extern "C" void kernel_launch(void* const* d_in, const int* in_sizes, int n_in,
                              void* d_out, int out_size)
{
    const float* rois   = (const float*)d_in[0];
    const float* rpn    = (const float*)d_in[1];
    const float* scores = (const float*)d_in[2];
    float* out = (float*)d_out;

    trnms_kernel<<<N_ROWS, THREADS>>>(rois, rpn, scores, out);
}